// round 4
// baseline (speedup 1.0000x reference)
#include <cuda_runtime.h>
#include <cstdint>

// x: [N=64, C=512, H=56, W=56] fp32. 2:4 structured sparsity along C:
// within each group of 4 channels (same n,h,w), zero the 2 smallest-|x|
// entries (ties: lower channel index dropped first, matching jax top_k).
//
// R4: R1 structure (4 float4 loads/thread), with
//  - 32-bit index math (max float4 index 25.7M < 2^31)
//  - plain loads (best DRAM% in R1) + .cs stores (output never re-read)
//  - __launch_bounds__(256,8) to pin regs<=32 (100% theoretical occ)

static constexpr int N_DIM  = 64;
static constexpr int C_DIM  = 512;
static constexpr int HW     = 56 * 56;          // 3136
static constexpr int HW4    = HW / 4;           // 784 float4 per channel plane
static constexpr int GROUPS = C_DIM / 4;        // 128
static constexpr int TOTAL_T = N_DIM * GROUPS * HW4; // 6,422,528 (fits int)

// keep element i iff at least 2 of the other 3 are "strictly smaller"
// under less(j,i) = (|a_j| < |a_i|) || (|a_j| == |a_i| && j < i).
__device__ __forceinline__ void mask4(float& x0, float& x1, float& x2, float& x3) {
    float a0 = fabsf(x0), a1 = fabsf(x1), a2 = fabsf(x2), a3 = fabsf(x3);
    int r0 = 0, r1 = 0, r2 = 0, r3 = 0;
    if (a0 <= a1) r1++; else r0++;   // less(0,1)=a0<=a1 ; less(1,0)=a1<a0
    if (a0 <= a2) r2++; else r0++;
    if (a0 <= a3) r3++; else r0++;
    if (a1 <= a2) r2++; else r1++;
    if (a1 <= a3) r3++; else r1++;
    if (a2 <= a3) r3++; else r2++;
    x0 = (r0 >= 2) ? x0 : 0.0f;
    x1 = (r1 >= 2) ? x1 : 0.0f;
    x2 = (r2 >= 2) ? x2 : 0.0f;
    x3 = (r3 >= 2) ? x3 : 0.0f;
}

__global__ void __launch_bounds__(256, 8)
sparsity24_kernel(const float4* __restrict__ x4, float4* __restrict__ o4) {
    int t = blockIdx.x * 256 + threadIdx.x;
    if (t >= TOTAL_T) return;

    // decode: t -> (ng, hw4); constant-divisor -> mul-shift in SASS
    int hw4 = t % HW4;
    int ng  = t / HW4;

    int base = ng * (4 * HW4) + hw4;   // max 25,690,112 < 2^31

    float4 v0 = x4[base];
    float4 v1 = x4[base + HW4];
    float4 v2 = x4[base + 2 * HW4];
    float4 v3 = x4[base + 3 * HW4];

    mask4(v0.x, v1.x, v2.x, v3.x);
    mask4(v0.y, v1.y, v2.y, v3.y);
    mask4(v0.z, v1.z, v2.z, v3.z);
    mask4(v0.w, v1.w, v2.w, v3.w);

    __stcs(&o4[base],           v0);
    __stcs(&o4[base + HW4],     v1);
    __stcs(&o4[base + 2 * HW4], v2);
    __stcs(&o4[base + 3 * HW4], v3);
}

extern "C" void kernel_launch(void* const* d_in, const int* in_sizes, int n_in,
                              void* d_out, int out_size) {
    const float4* x4 = (const float4*)d_in[0];
    float4* o4 = (float4*)d_out;
    int blocks = (TOTAL_T + 255) / 256;
    sparsity24_kernel<<<blocks, 256>>>(x4, o4);
}